// round 1
// baseline (speedup 1.0000x reference)
#include <cuda_runtime.h>
#include <math.h>

// Problem constants
#define T_TOK 4096
#define HDIM  2048
#define FDIM  4096
#define NEXP  8
#define TOPK  2
#define NASSIGN (T_TOK * TOPK)   // 8192 (every token routed to exactly 2 experts)

// GEMM tiling
#define BM 128
#define BN 128
#define BK 16

// ---------------------------------------------------------------------------
// Scratch (static __device__ — no allocation inside kernel_launch)
// ---------------------------------------------------------------------------
__device__ float g_h[(size_t)NASSIGN * (2 * FDIM)]; // 268 MB: up-proj result per assignment
__device__ float g_s[(size_t)NASSIGN * FDIM];       // 134 MB: swiglu result per assignment
__device__ int   g_eid[T_TOK * TOPK];               // per-token expert ids
__device__ float g_wt [T_TOK * TOPK];               // per-token routing weights
__device__ int   g_tok[NASSIGN];                    // assignment -> token (sorted by expert)
__device__ float g_w  [NASSIGN];                    // assignment -> routing weight
__device__ int   g_cnt [NEXP];
__device__ int   g_off [NEXP + 1];
__device__ int   g_fill[NEXP];

// ---------------------------------------------------------------------------
// Packed fp32x2 helpers (Blackwell f32x2 pipe: doubles FFMA throughput)
// ---------------------------------------------------------------------------
__device__ __forceinline__ unsigned long long ffma2(unsigned long long a,
                                                    unsigned long long b,
                                                    unsigned long long c) {
    unsigned long long d;
    asm("fma.rn.f32x2 %0, %1, %2, %3;" : "=l"(d) : "l"(a), "l"(b), "l"(c));
    return d;
}
__device__ __forceinline__ unsigned long long pack2(float x) {
    unsigned long long d;
    asm("mov.b64 %0, {%1, %1};" : "=l"(d) : "f"(x));
    return d;
}

// ---------------------------------------------------------------------------
// 0) reset: zero output + expert counters (out is poisoned to 0xAA each run)
// ---------------------------------------------------------------------------
__global__ void reset_kernel(float* __restrict__ out) {
    size_t i = (size_t)blockIdx.x * blockDim.x + threadIdx.x;
    out[i] = 0.0f; // grid sized exactly T_TOK*HDIM
    if (blockIdx.x == 0 && threadIdx.x < NEXP) g_cnt[threadIdx.x] = 0;
}

// ---------------------------------------------------------------------------
// 1) gate: logits over 8 experts, top-2 (first-index tie-break like jax),
//    softmax over the 2 selected logits. One warp per token.
// ---------------------------------------------------------------------------
__global__ void gate_kernel(const float* __restrict__ x, const float* __restrict__ gw) {
    int warp = threadIdx.x >> 5, lane = threadIdx.x & 31;
    int t = blockIdx.x * (blockDim.x >> 5) + warp;
    if (t >= T_TOK) return;

    float acc[NEXP];
#pragma unroll
    for (int e = 0; e < NEXP; e++) acc[e] = 0.0f;

    const float* xp = x + (size_t)t * HDIM;
    for (int h = lane; h < HDIM; h += 32) {
        float xv = xp[h];
#pragma unroll
        for (int e = 0; e < NEXP; e++) acc[e] += xv * gw[e * HDIM + h];
    }
#pragma unroll
    for (int e = 0; e < NEXP; e++)
#pragma unroll
        for (int o = 16; o > 0; o >>= 1)
            acc[e] += __shfl_xor_sync(0xffffffffu, acc[e], o);

    if (lane == 0) {
        int e0 = 0; float l0 = acc[0];
#pragma unroll
        for (int e = 1; e < NEXP; e++) if (acc[e] > l0) { l0 = acc[e]; e0 = e; }
        int e1 = -1; float l1 = -INFINITY;
#pragma unroll
        for (int e = 0; e < NEXP; e++) if (e != e0 && acc[e] > l1) { l1 = acc[e]; e1 = e; }
        float p  = expf(l1 - l0);
        float s  = 1.0f / (1.0f + p);
        g_eid[2 * t]     = e0;  g_eid[2 * t + 1] = e1;
        g_wt [2 * t]     = s;   g_wt [2 * t + 1] = p * s;
        atomicAdd(&g_cnt[e0], 1);
        atomicAdd(&g_cnt[e1], 1);
    }
}

// ---------------------------------------------------------------------------
// 2) scan: exclusive prefix over 8 expert counts (single thread — tiny)
// ---------------------------------------------------------------------------
__global__ void scan_kernel() {
    int s = 0;
    for (int e = 0; e < NEXP; e++) { g_off[e] = s; s += g_cnt[e]; g_fill[e] = 0; }
    g_off[NEXP] = s;
}

// ---------------------------------------------------------------------------
// 3) scatter: build expert-sorted assignment lists
// ---------------------------------------------------------------------------
__global__ void scatter_kernel() {
    int t = blockIdx.x * blockDim.x + threadIdx.x;
    if (t >= T_TOK) return;
#pragma unroll
    for (int k = 0; k < TOPK; k++) {
        int e = g_eid[2 * t + k];
        int pos = g_off[e] + atomicAdd(&g_fill[e], 1);
        g_tok[pos] = t;
        g_w[pos]   = g_wt[2 * t + k];
    }
}

// ---------------------------------------------------------------------------
// 4) GEMM1: h[rows, 2F] = gather(x)[rows, H] @ w1[e]   (per-expert row ranges)
//    128x128x16 tile, 256 threads, 8x8 microtile via packed f32x2 FMAs
// ---------------------------------------------------------------------------
__global__ __launch_bounds__(256, 2) void gemm1_kernel(
    const float* __restrict__ x, const float* __restrict__ w1) {
    const int e     = blockIdx.z;
    const int row0  = g_off[e];
    const int nrows = g_off[e + 1] - row0;
    const int mbase = blockIdx.y * BM;
    if (mbase >= nrows) return;
    const int nbase = blockIdx.x * BN; // over 2F = 8192

    __shared__ float As[BK][BM + 4];
    __shared__ float Bs[BK][BN + 4];

    const int tid = threadIdx.x;
    const int tx = tid & 15, ty = tid >> 4;
    const int m0 = ty * 8, n0 = tx * 8;

    const float* Bbase = w1 + (size_t)e * HDIM * (2 * FDIM) + nbase;

    // A-gather setup: each thread owns 2 float4 loads of the A tile
    const float* aptr[2];
    bool aval[2];
    int  akq[2], amm[2];
#pragma unroll
    for (int r = 0; r < 2; r++) {
        int f = tid + 256 * r;
        int m = f >> 2, kq = f & 3;
        amm[r] = m; akq[r] = kq;
        int gm = mbase + m;
        aval[r] = (gm < nrows);
        int tok = aval[r] ? g_tok[row0 + gm] : 0;
        aptr[r] = x + (size_t)tok * HDIM + kq * 4;
    }
    int bk[2], bn[2];
#pragma unroll
    for (int r = 0; r < 2; r++) { int f = tid + 256 * r; bk[r] = f >> 5; bn[r] = (f & 31) * 4; }

    unsigned long long acc[8][4];
#pragma unroll
    for (int i = 0; i < 8; i++)
#pragma unroll
        for (int j = 0; j < 4; j++) acc[i][j] = 0ull;

    for (int k0 = 0; k0 < HDIM; k0 += BK) {
#pragma unroll
        for (int r = 0; r < 2; r++) {
            float4 v = aval[r] ? *reinterpret_cast<const float4*>(aptr[r] + k0)
                               : make_float4(0.f, 0.f, 0.f, 0.f);
            As[akq[r] * 4 + 0][amm[r]] = v.x;
            As[akq[r] * 4 + 1][amm[r]] = v.y;
            As[akq[r] * 4 + 2][amm[r]] = v.z;
            As[akq[r] * 4 + 3][amm[r]] = v.w;
            float4 bv = *reinterpret_cast<const float4*>(
                Bbase + (size_t)(k0 + bk[r]) * (2 * FDIM) + bn[r]);
            *reinterpret_cast<float4*>(&Bs[bk[r]][bn[r]]) = bv;
        }
        __syncthreads();
#pragma unroll
        for (int kk = 0; kk < BK; kk++) {
            float4 a0 = *reinterpret_cast<const float4*>(&As[kk][m0]);
            float4 a1 = *reinterpret_cast<const float4*>(&As[kk][m0 + 4]);
            unsigned long long bp0 = *reinterpret_cast<const unsigned long long*>(&Bs[kk][n0]);
            unsigned long long bp1 = *reinterpret_cast<const unsigned long long*>(&Bs[kk][n0 + 2]);
            unsigned long long bp2 = *reinterpret_cast<const unsigned long long*>(&Bs[kk][n0 + 4]);
            unsigned long long bp3 = *reinterpret_cast<const unsigned long long*>(&Bs[kk][n0 + 6]);
            float av[8] = {a0.x, a0.y, a0.z, a0.w, a1.x, a1.y, a1.z, a1.w};
#pragma unroll
            for (int i = 0; i < 8; i++) {
                unsigned long long ap = pack2(av[i]);
                acc[i][0] = ffma2(ap, bp0, acc[i][0]);
                acc[i][1] = ffma2(ap, bp1, acc[i][1]);
                acc[i][2] = ffma2(ap, bp2, acc[i][2]);
                acc[i][3] = ffma2(ap, bp3, acc[i][3]);
            }
        }
        __syncthreads();
    }
#pragma unroll
    for (int i = 0; i < 8; i++) {
        int gm = mbase + m0 + i;
        if (gm < nrows) {
            float* dst = g_h + (size_t)(row0 + gm) * (2 * FDIM) + nbase + n0;
#pragma unroll
            for (int j = 0; j < 4; j++)
                *reinterpret_cast<float2*>(dst + 2 * j) =
                    *reinterpret_cast<float2*>(&acc[i][j]);
        }
    }
}

// ---------------------------------------------------------------------------
// 5) swiglu: S = silu(h[:, :F]) * h[:, F:]
// ---------------------------------------------------------------------------
__global__ void swiglu_kernel() {
    size_t i = (size_t)blockIdx.x * blockDim.x + threadIdx.x; // over NASSIGN*FDIM/4
    size_t row = i / (FDIM / 4);
    int    c4  = (int)(i % (FDIM / 4));
    const float4 a = *reinterpret_cast<const float4*>(&g_h[row * (2 * FDIM) + c4 * 4]);
    const float4 b = *reinterpret_cast<const float4*>(&g_h[row * (2 * FDIM) + FDIM + c4 * 4]);
    float4 s;
    s.x = a.x / (1.0f + expf(-a.x)) * b.x;
    s.y = a.y / (1.0f + expf(-a.y)) * b.y;
    s.z = a.z / (1.0f + expf(-a.z)) * b.z;
    s.w = a.w / (1.0f + expf(-a.w)) * b.w;
    *reinterpret_cast<float4*>(&g_s[row * FDIM + c4 * 4]) = s;
}

// ---------------------------------------------------------------------------
// 6) GEMM2: Y[rows, H] = S[rows, F] @ w2[e]; out[tok] += w * Y (atomic)
// ---------------------------------------------------------------------------
__global__ __launch_bounds__(256, 2) void gemm2_kernel(
    const float* __restrict__ w2, float* __restrict__ out) {
    const int e     = blockIdx.z;
    const int row0  = g_off[e];
    const int nrows = g_off[e + 1] - row0;
    const int mbase = blockIdx.y * BM;
    if (mbase >= nrows) return;
    const int nbase = blockIdx.x * BN; // over H = 2048

    __shared__ float As[BK][BM + 4];
    __shared__ float Bs[BK][BN + 4];

    const int tid = threadIdx.x;
    const int tx = tid & 15, ty = tid >> 4;
    const int m0 = ty * 8, n0 = tx * 8;

    const float* Bbase = w2 + (size_t)e * FDIM * HDIM + nbase;

    const float* aptr[2];
    bool aval[2];
    int  akq[2], amm[2];
#pragma unroll
    for (int r = 0; r < 2; r++) {
        int f = tid + 256 * r;
        int m = f >> 2, kq = f & 3;
        amm[r] = m; akq[r] = kq;
        int gm = mbase + m;
        aval[r] = (gm < nrows);
        int rr = aval[r] ? (row0 + gm) : 0;
        aptr[r] = g_s + (size_t)rr * FDIM + kq * 4;
    }
    int bk[2], bn[2];
#pragma unroll
    for (int r = 0; r < 2; r++) { int f = tid + 256 * r; bk[r] = f >> 5; bn[r] = (f & 31) * 4; }

    unsigned long long acc[8][4];
#pragma unroll
    for (int i = 0; i < 8; i++)
#pragma unroll
        for (int j = 0; j < 4; j++) acc[i][j] = 0ull;

    for (int k0 = 0; k0 < FDIM; k0 += BK) {
#pragma unroll
        for (int r = 0; r < 2; r++) {
            float4 v = aval[r] ? *reinterpret_cast<const float4*>(aptr[r] + k0)
                               : make_float4(0.f, 0.f, 0.f, 0.f);
            As[akq[r] * 4 + 0][amm[r]] = v.x;
            As[akq[r] * 4 + 1][amm[r]] = v.y;
            As[akq[r] * 4 + 2][amm[r]] = v.z;
            As[akq[r] * 4 + 3][amm[r]] = v.w;
            float4 bv = *reinterpret_cast<const float4*>(
                Bbase + (size_t)(k0 + bk[r]) * HDIM + bn[r]);
            *reinterpret_cast<float4*>(&Bs[bk[r]][bn[r]]) = bv;
        }
        __syncthreads();
#pragma unroll
        for (int kk = 0; kk < BK; kk++) {
            float4 a0 = *reinterpret_cast<const float4*>(&As[kk][m0]);
            float4 a1 = *reinterpret_cast<const float4*>(&As[kk][m0 + 4]);
            unsigned long long bp0 = *reinterpret_cast<const unsigned long long*>(&Bs[kk][n0]);
            unsigned long long bp1 = *reinterpret_cast<const unsigned long long*>(&Bs[kk][n0 + 2]);
            unsigned long long bp2 = *reinterpret_cast<const unsigned long long*>(&Bs[kk][n0 + 4]);
            unsigned long long bp3 = *reinterpret_cast<const unsigned long long*>(&Bs[kk][n0 + 6]);
            float av[8] = {a0.x, a0.y, a0.z, a0.w, a1.x, a1.y, a1.z, a1.w};
#pragma unroll
            for (int i = 0; i < 8; i++) {
                unsigned long long ap = pack2(av[i]);
                acc[i][0] = ffma2(ap, bp0, acc[i][0]);
                acc[i][1] = ffma2(ap, bp1, acc[i][1]);
                acc[i][2] = ffma2(ap, bp2, acc[i][2]);
                acc[i][3] = ffma2(ap, bp3, acc[i][3]);
            }
        }
        __syncthreads();
    }
#pragma unroll
    for (int i = 0; i < 8; i++) {
        int gm = mbase + m0 + i;
        if (gm < nrows) {
            int   tok = g_tok[row0 + gm];
            float w   = g_w[row0 + gm];
            float* dst = out + (size_t)tok * HDIM + nbase + n0;
#pragma unroll
            for (int j = 0; j < 4; j++) {
                float2 v = *reinterpret_cast<float2*>(&acc[i][j]);
                atomicAdd(&dst[2 * j],     w * v.x);
                atomicAdd(&dst[2 * j + 1], w * v.y);
            }
        }
    }
}

// ---------------------------------------------------------------------------
// launch
// ---------------------------------------------------------------------------
extern "C" void kernel_launch(void* const* d_in, const int* in_sizes, int n_in,
                              void* d_out, int out_size) {
    const float* x   = (const float*)d_in[0]; // [T, H]
    const float* gw  = (const float*)d_in[1]; // [E, H]
    const float* w1  = (const float*)d_in[2]; // [E, H, 2F]
    const float* w2  = (const float*)d_in[3]; // [E, F, H]
    float* out = (float*)d_out;               // [T, H]

    // 0) zero output + expert counters   (T*H = 8192*1024 exactly)
    reset_kernel<<<8192, 1024>>>(out);
    // 1) gate + top2 + softmax (1 warp per token)
    gate_kernel<<<T_TOK / 8, 256>>>(x, gw);
    // 2) offsets
    scan_kernel<<<1, 1>>>();
    // 3) expert-sorted assignment lists
    scatter_kernel<<<T_TOK / 256, 256>>>();
    // 4) up-projection (grouped, gathered A)
    gemm1_kernel<<<dim3(2 * FDIM / BN, T_TOK / BM, NEXP), 256>>>(x, w1);
    // 5) swiglu
    swiglu_kernel<<<(NASSIGN * (FDIM / 4)) / 256, 256>>>();
    // 6) down-projection + weighted scatter-add
    gemm2_kernel<<<dim3(HDIM / BN, T_TOK / BM, NEXP), 256>>>(w2, out);
}

// round 3
// speedup vs baseline: 2.3822x; 2.3822x over previous
#include <cuda_runtime.h>
#include <cuda_bf16.h>
#include <cstdint>
#include <math.h>

// Problem constants
#define T_TOK 4096
#define HDIM  2048
#define FDIM  4096
#define NEXP  8
#define TOPK  2
#define NASSIGN (T_TOK * TOPK)   // 8192

// GEMM tiling (sm80-style HMMA pipeline)
#define BM 128
#define BN 256
#define BK 32
#define MTILES_MAX 16            // covers up to 2048 rows/expert (mean 1024, sigma~30)

#define A_ROW_B 80               // 32 bf16 = 64B + 16B pad (conflict-free ldmatrix)
#define B_ROW_B 528              // 256 bf16 = 512B + 16B pad
#define OFF_AHI 0
#define OFF_ALO (BM * A_ROW_B)               // 10240
#define OFF_BHI (2 * BM * A_ROW_B)           // 20480
#define OFF_BLO (OFF_BHI + BK * B_ROW_B)     // 37376
#define STAGE_B (OFF_BLO + BK * B_ROW_B)     // 54272
#define SMEM_TOTAL (3 * STAGE_B)             // 162816

// ---------------------------------------------------------------------------
// Scratch (__device__ globals — no allocation anywhere)
// ---------------------------------------------------------------------------
__device__ __nv_bfloat16 g_xhi[(size_t)T_TOK * HDIM];
__device__ __nv_bfloat16 g_xlo[(size_t)T_TOK * HDIM];
// w1 split + column-interleaved: [E][H][2F], col n' = 2f -> a_f, 2f+1 -> b_f
__device__ __nv_bfloat16 g_w1i_hi[(size_t)NEXP * HDIM * 2 * FDIM];
__device__ __nv_bfloat16 g_w1i_lo[(size_t)NEXP * HDIM * 2 * FDIM];
// w2 split, natural layout [E][F][H]
__device__ __nv_bfloat16 g_w2s_hi[(size_t)NEXP * FDIM * HDIM];
__device__ __nv_bfloat16 g_w2s_lo[(size_t)NEXP * FDIM * HDIM];
// swiglu output (split bf16): [NASSIGN][F]
__device__ __nv_bfloat16 g_s_hi[(size_t)NASSIGN * FDIM];
__device__ __nv_bfloat16 g_s_lo[(size_t)NASSIGN * FDIM];

__device__ int   g_eid[T_TOK * TOPK];
__device__ float g_wt [T_TOK * TOPK];
__device__ int   g_tok[NASSIGN];
__device__ float g_w  [NASSIGN];
__device__ int   g_cnt [NEXP];
__device__ int   g_off [NEXP + 1];
__device__ int   g_fill[NEXP];

// ---------------------------------------------------------------------------
// PTX helpers (all base-ISA, valid on sm_103 target)
// ---------------------------------------------------------------------------
__device__ __forceinline__ void cp16(uint32_t dst, const void* src, uint32_t sz) {
    asm volatile("cp.async.cg.shared.global [%0], [%1], 16, %2;"
                 :: "r"(dst), "l"(src), "r"(sz) : "memory");
}
__device__ __forceinline__ void cp_commit() {
    asm volatile("cp.async.commit_group;" ::: "memory");
}
__device__ __forceinline__ void cp_wait1() {
    asm volatile("cp.async.wait_group 1;" ::: "memory");
}
__device__ __forceinline__ void cp_wait0() {
    asm volatile("cp.async.wait_group 0;" ::: "memory");
}
__device__ __forceinline__ void ldsm4(uint32_t* r, uint32_t a) {
    asm volatile("ldmatrix.sync.aligned.m8n8.x4.shared.b16 {%0,%1,%2,%3}, [%4];"
                 : "=r"(r[0]), "=r"(r[1]), "=r"(r[2]), "=r"(r[3]) : "r"(a));
}
__device__ __forceinline__ void ldsm4t(uint32_t* r, uint32_t a) {
    asm volatile("ldmatrix.sync.aligned.m8n8.x4.trans.shared.b16 {%0,%1,%2,%3}, [%4];"
                 : "=r"(r[0]), "=r"(r[1]), "=r"(r[2]), "=r"(r[3]) : "r"(a));
}
__device__ __forceinline__ void mma4(float* c, const uint32_t* a, uint32_t b0, uint32_t b1) {
    asm volatile("mma.sync.aligned.m16n8k16.row.col.f32.bf16.bf16.f32 "
                 "{%0,%1,%2,%3}, {%4,%5,%6,%7}, {%8,%9}, {%0,%1,%2,%3};"
                 : "+f"(c[0]), "+f"(c[1]), "+f"(c[2]), "+f"(c[3])
                 : "r"(a[0]), "r"(a[1]), "r"(a[2]), "r"(a[3]), "r"(b0), "r"(b1));
}

__device__ __forceinline__ void split_bf16(float v, __nv_bfloat16& h, __nv_bfloat16& l) {
    h = __float2bfloat16(v);
    l = __float2bfloat16(v - __bfloat162float(h));
}

// ---------------------------------------------------------------------------
// 0) reset output + counters
// ---------------------------------------------------------------------------
__global__ void reset_kernel(float* __restrict__ out) {
    size_t i = (size_t)blockIdx.x * blockDim.x + threadIdx.x;
    out[i] = 0.0f;  // grid sized exactly T_TOK*HDIM
    if (blockIdx.x == 0 && threadIdx.x < NEXP) g_cnt[threadIdx.x] = 0;
}

// ---------------------------------------------------------------------------
// 1) gate: top-2 + softmax (proven in R1)
// ---------------------------------------------------------------------------
__global__ void gate_kernel(const float* __restrict__ x, const float* __restrict__ gw) {
    int warp = threadIdx.x >> 5, lane = threadIdx.x & 31;
    int t = blockIdx.x * (blockDim.x >> 5) + warp;
    if (t >= T_TOK) return;
    float acc[NEXP];
#pragma unroll
    for (int e = 0; e < NEXP; e++) acc[e] = 0.0f;
    const float* xp = x + (size_t)t * HDIM;
    for (int h = lane; h < HDIM; h += 32) {
        float xv = xp[h];
#pragma unroll
        for (int e = 0; e < NEXP; e++) acc[e] += xv * gw[e * HDIM + h];
    }
#pragma unroll
    for (int e = 0; e < NEXP; e++)
#pragma unroll
        for (int o = 16; o > 0; o >>= 1)
            acc[e] += __shfl_xor_sync(0xffffffffu, acc[e], o);
    if (lane == 0) {
        int e0 = 0; float l0 = acc[0];
#pragma unroll
        for (int e = 1; e < NEXP; e++) if (acc[e] > l0) { l0 = acc[e]; e0 = e; }
        int e1 = -1; float l1 = -INFINITY;
#pragma unroll
        for (int e = 0; e < NEXP; e++) if (e != e0 && acc[e] > l1) { l1 = acc[e]; e1 = e; }
        float p = expf(l1 - l0);
        float s = 1.0f / (1.0f + p);
        g_eid[2 * t] = e0;  g_eid[2 * t + 1] = e1;
        g_wt [2 * t] = s;   g_wt [2 * t + 1] = p * s;
        atomicAdd(&g_cnt[e0], 1);
        atomicAdd(&g_cnt[e1], 1);
    }
}

__global__ void scan_kernel() {
    int s = 0;
    for (int e = 0; e < NEXP; e++) { g_off[e] = s; s += g_cnt[e]; g_fill[e] = 0; }
    g_off[NEXP] = s;
}

__global__ void scatter_kernel() {
    int t = blockIdx.x * blockDim.x + threadIdx.x;
    if (t >= T_TOK) return;
#pragma unroll
    for (int k = 0; k < TOPK; k++) {
        int e = g_eid[2 * t + k];
        int pos = g_off[e] + atomicAdd(&g_fill[e], 1);
        g_tok[pos] = t;
        g_w[pos]   = g_wt[2 * t + k];
    }
}

// ---------------------------------------------------------------------------
// 2) conversions: fp32 -> split bf16 (elementwise, no transposes needed)
// ---------------------------------------------------------------------------
__global__ void convert_x_kernel(const float* __restrict__ x) {
    size_t i = ((size_t)blockIdx.x * blockDim.x + threadIdx.x) * 4;
    float4 v = *reinterpret_cast<const float4*>(x + i);
    __nv_bfloat16 h[4], l[4];
    split_bf16(v.x, h[0], l[0]); split_bf16(v.y, h[1], l[1]);
    split_bf16(v.z, h[2], l[2]); split_bf16(v.w, h[3], l[3]);
    *reinterpret_cast<uint2*>(g_xhi + i) = *reinterpret_cast<uint2*>(h);
    *reinterpret_cast<uint2*>(g_xlo + i) = *reinterpret_cast<uint2*>(l);
}

// w1 [E][H][2F]: interleave a/b columns -> [E][H][2F] with n' = 2f / 2f+1
__global__ void convert_w1i_kernel(const float* __restrict__ w1) {
    size_t i = (size_t)blockIdx.x * blockDim.x + threadIdx.x; // over E*H*(F/4)
    size_t ek = i / (FDIM / 4);
    int f0 = (int)(i % (FDIM / 4)) * 4;
    const float* src = w1 + ek * (size_t)(2 * FDIM);
    float4 va = *reinterpret_cast<const float4*>(src + f0);
    float4 vb = *reinterpret_cast<const float4*>(src + FDIM + f0);
    __nv_bfloat16 hi[8], lo[8];
    split_bf16(va.x, hi[0], lo[0]); split_bf16(vb.x, hi[1], lo[1]);
    split_bf16(va.y, hi[2], lo[2]); split_bf16(vb.y, hi[3], lo[3]);
    split_bf16(va.z, hi[4], lo[4]); split_bf16(vb.z, hi[5], lo[5]);
    split_bf16(va.w, hi[6], lo[6]); split_bf16(vb.w, hi[7], lo[7]);
    size_t o = ek * (size_t)(2 * FDIM) + 2 * f0;
    *reinterpret_cast<uint4*>(g_w1i_hi + o) = *reinterpret_cast<uint4*>(hi);
    *reinterpret_cast<uint4*>(g_w1i_lo + o) = *reinterpret_cast<uint4*>(lo);
}

// w2 [E][F][H]: pure elementwise split
__global__ void convert_w2s_kernel(const float* __restrict__ w2) {
    size_t i = ((size_t)blockIdx.x * blockDim.x + threadIdx.x) * 4;
    float4 v = *reinterpret_cast<const float4*>(w2 + i);
    __nv_bfloat16 h[4], l[4];
    split_bf16(v.x, h[0], l[0]); split_bf16(v.y, h[1], l[1]);
    split_bf16(v.z, h[2], l[2]); split_bf16(v.w, h[3], l[3]);
    *reinterpret_cast<uint2*>(g_w2s_hi + i) = *reinterpret_cast<uint2*>(h);
    *reinterpret_cast<uint2*>(g_w2s_lo + i) = *reinterpret_cast<uint2*>(l);
}

// ---------------------------------------------------------------------------
// 3) grouped HMMA GEMM, 3-term split-bf16, 3-stage cp.async pipeline.
//    G1=true : D = gather(x) @ w1i, fused swiglu -> g_s (split bf16)
//    G1=false: Y = S @ w2,        weighted atomic scatter -> out
// ---------------------------------------------------------------------------
template<bool G1>
__global__ __launch_bounds__(256, 1) void gemm_tc(float* __restrict__ out) {
    constexpr int KDIM = G1 ? HDIM : FDIM;
    constexpr int NCH  = KDIM / BK;
    constexpr int LDB  = G1 ? (2 * FDIM) : HDIM;

    const int tid = threadIdx.x;
    const int e = blockIdx.z;
    const int row0 = g_off[e];
    const int nrows = g_off[e + 1] - row0;
    const int mbase = blockIdx.y * BM;
    if (mbase >= nrows) return;
    const int nbase = blockIdx.x * BN;

    extern __shared__ __align__(128) char dsm[];
    const uint32_t smem0 = (uint32_t)__cvta_generic_to_shared(dsm);

    // ---- loader setup ----
    const __nv_bfloat16 *ahi[2], *alo[2];
    uint32_t adst[2], asz[2];
#pragma unroll
    for (int r = 0; r < 2; r++) {
        int idx = tid + 256 * r;
        int m = idx >> 2, cq = idx & 3;
        int gm = mbase + m;
        bool ok = gm < nrows;
        int rowid = ok ? (row0 + gm) : 0;
        if (G1) {
            int tok = ok ? g_tok[rowid] : 0;
            ahi[r] = g_xhi + (size_t)tok * HDIM + cq * 8;
            alo[r] = g_xlo + (size_t)tok * HDIM + cq * 8;
        } else {
            ahi[r] = g_s_hi + (size_t)rowid * FDIM + cq * 8;
            alo[r] = g_s_lo + (size_t)rowid * FDIM + cq * 8;
        }
        adst[r] = (uint32_t)(m * A_ROW_B + cq * 16);
        asz[r] = ok ? 16u : 0u;
    }
    const __nv_bfloat16 *bhi[4], *blo[4];
    uint32_t bdst[4];
#pragma unroll
    for (int j = 0; j < 4; j++) {
        int idx = tid + 256 * j;
        int row = idx >> 5, cq = idx & 31;
        size_t o;
        if (G1) o = ((size_t)e * HDIM + row) * (size_t)(2 * FDIM) + nbase + cq * 8;
        else    o = ((size_t)e * FDIM + row) * (size_t)HDIM + nbase + cq * 8;
        bhi[j] = (G1 ? g_w1i_hi : g_w2s_hi) + o;
        blo[j] = (G1 ? g_w1i_lo : g_w2s_lo) + o;
        bdst[j] = (uint32_t)(row * B_ROW_B + cq * 16);
    }

    auto load_stage = [&](int ck) {
        uint32_t sb = smem0 + (ck % 3) * STAGE_B;
        size_t ka = (size_t)ck * BK;
        size_t kb = (size_t)ck * BK * LDB;
#pragma unroll
        for (int r = 0; r < 2; r++) {
            cp16(sb + OFF_AHI + adst[r], ahi[r] + ka, asz[r]);
            cp16(sb + OFF_ALO + adst[r], alo[r] + ka, asz[r]);
        }
#pragma unroll
        for (int j = 0; j < 4; j++) {
            cp16(sb + OFF_BHI + bdst[j], bhi[j] + kb, 16u);
            cp16(sb + OFF_BLO + bdst[j], blo[j] + kb, 16u);
        }
    };

    float c[4][8][4];
#pragma unroll
    for (int i = 0; i < 4; i++)
#pragma unroll
        for (int j = 0; j < 8; j++)
#pragma unroll
            for (int q = 0; q < 4; q++) c[i][j][q] = 0.0f;

    const int lane = tid & 31, wid = tid >> 5;
    const int wm = wid >> 2, wn = wid & 3;
    const int lr = lane & 15, lc = lane >> 4;

    load_stage(0); cp_commit();
    load_stage(1); cp_commit();

    for (int ck = 0; ck < NCH; ck++) {
        cp_wait1();
        __syncthreads();
        if (ck + 2 < NCH) load_stage(ck + 2);
        cp_commit();

        uint32_t sb = smem0 + (ck % 3) * STAGE_B;
#pragma unroll
        for (int ko = 0; ko < 2; ko++) {
            uint32_t aAh = sb + OFF_AHI + (wm * 64 + lr) * A_ROW_B + ko * 32 + lc * 16;
            uint32_t aAl = sb + OFF_ALO + (wm * 64 + lr) * A_ROW_B + ko * 32 + lc * 16;
            uint32_t aBh = sb + OFF_BHI + (ko * 16 + lr) * B_ROW_B + wn * 128 + lc * 16;
            uint32_t aBl = sb + OFF_BLO + (ko * 16 + lr) * B_ROW_B + wn * 128 + lc * 16;
            uint32_t a[4][4], b[4][4];
            // term 1: Ahi x Bhi
#pragma unroll
            for (int mi = 0; mi < 4; mi++) ldsm4(a[mi], aAh + mi * 16 * A_ROW_B);
#pragma unroll
            for (int nj = 0; nj < 4; nj++) ldsm4t(b[nj], aBh + nj * 32);
#pragma unroll
            for (int mi = 0; mi < 4; mi++)
#pragma unroll
                for (int nj = 0; nj < 4; nj++) {
                    mma4(c[mi][2 * nj],     a[mi], b[nj][0], b[nj][1]);
                    mma4(c[mi][2 * nj + 1], a[mi], b[nj][2], b[nj][3]);
                }
            // term 2: Ahi x Blo
#pragma unroll
            for (int nj = 0; nj < 4; nj++) ldsm4t(b[nj], aBl + nj * 32);
#pragma unroll
            for (int mi = 0; mi < 4; mi++)
#pragma unroll
                for (int nj = 0; nj < 4; nj++) {
                    mma4(c[mi][2 * nj],     a[mi], b[nj][0], b[nj][1]);
                    mma4(c[mi][2 * nj + 1], a[mi], b[nj][2], b[nj][3]);
                }
            // term 3: Alo x Bhi
#pragma unroll
            for (int mi = 0; mi < 4; mi++) ldsm4(a[mi], aAl + mi * 16 * A_ROW_B);
#pragma unroll
            for (int nj = 0; nj < 4; nj++) ldsm4t(b[nj], aBh + nj * 32);
#pragma unroll
            for (int mi = 0; mi < 4; mi++)
#pragma unroll
                for (int nj = 0; nj < 4; nj++) {
                    mma4(c[mi][2 * nj],     a[mi], b[nj][0], b[nj][1]);
                    mma4(c[mi][2 * nj + 1], a[mi], b[nj][2], b[nj][3]);
                }
        }
    }
    cp_wait0();

    // ---- epilogue ----
    if constexpr (G1) {
        // acc cols are interleaved (a,b) pairs: c[..][0]=a, c[..][1]=b (row gr),
        // c[..][2]=a, c[..][3]=b (row gr+8). SwiGLU entirely thread-local.
#pragma unroll
        for (int mi = 0; mi < 4; mi++) {
            int r0 = wm * 64 + mi * 16 + (lane >> 2);
            int gm0 = mbase + r0, gm1 = gm0 + 8;
            bool ok0 = gm0 < nrows, ok1 = gm1 < nrows;
            size_t s0 = (size_t)(row0 + gm0) * FDIM;
            size_t s1 = (size_t)(row0 + gm1) * FDIM;
#pragma unroll
            for (int n8 = 0; n8 < 8; n8++) {
                int f = (nbase >> 1) + wn * 32 + n8 * 4 + (lane & 3);
                if (ok0) {
                    float a = c[mi][n8][0], bb = c[mi][n8][1];
                    float sv = a / (1.0f + expf(-a)) * bb;
                    __nv_bfloat16 h, l; split_bf16(sv, h, l);
                    g_s_hi[s0 + f] = h; g_s_lo[s0 + f] = l;
                }
                if (ok1) {
                    float a = c[mi][n8][2], bb = c[mi][n8][3];
                    float sv = a / (1.0f + expf(-a)) * bb;
                    __nv_bfloat16 h, l; split_bf16(sv, h, l);
                    g_s_hi[s1 + f] = h; g_s_lo[s1 + f] = l;
                }
            }
        }
    } else {
#pragma unroll
        for (int mi = 0; mi < 4; mi++) {
            int r0 = wm * 64 + mi * 16 + (lane >> 2);
            int gm0 = mbase + r0, gm1 = gm0 + 8;
            bool ok0 = gm0 < nrows, ok1 = gm1 < nrows;
            int tok0 = ok0 ? g_tok[row0 + gm0] : 0;
            int tok1 = ok1 ? g_tok[row0 + gm1] : 0;
            float w0 = ok0 ? g_w[row0 + gm0] : 0.0f;
            float w1v = ok1 ? g_w[row0 + gm1] : 0.0f;
            float* o0 = out + (size_t)tok0 * HDIM;
            float* o1 = out + (size_t)tok1 * HDIM;
#pragma unroll
            for (int n8 = 0; n8 < 8; n8++) {
                int col = nbase + wn * 64 + n8 * 8 + (lane & 3) * 2;
                if (ok0) {
                    atomicAdd(o0 + col,     w0 * c[mi][n8][0]);
                    atomicAdd(o0 + col + 1, w0 * c[mi][n8][1]);
                }
                if (ok1) {
                    atomicAdd(o1 + col,     w1v * c[mi][n8][2]);
                    atomicAdd(o1 + col + 1, w1v * c[mi][n8][3]);
                }
            }
        }
    }
}

// ---------------------------------------------------------------------------
// launch
// ---------------------------------------------------------------------------
extern "C" void kernel_launch(void* const* d_in, const int* in_sizes, int n_in,
                              void* d_out, int out_size) {
    const float* x  = (const float*)d_in[0]; // [T, H]
    const float* gw = (const float*)d_in[1]; // [E, H]
    const float* w1 = (const float*)d_in[2]; // [E, H, 2F]
    const float* w2 = (const float*)d_in[3]; // [E, F, H]
    float* out = (float*)d_out;              // [T, H]

    cudaFuncSetAttribute(gemm_tc<true>,  cudaFuncAttributeMaxDynamicSharedMemorySize, SMEM_TOTAL);
    cudaFuncSetAttribute(gemm_tc<false>, cudaFuncAttributeMaxDynamicSharedMemorySize, SMEM_TOTAL);

    reset_kernel<<<8192, 1024>>>(out);                     // T*H exactly
    gate_kernel<<<T_TOK / 8, 256>>>(x, gw);
    scan_kernel<<<1, 1>>>();
    scatter_kernel<<<T_TOK / 256, 256>>>();

    convert_x_kernel<<<(T_TOK * HDIM / 4) / 256, 256>>>(x);
    convert_w1i_kernel<<<(NEXP * HDIM * (FDIM / 4)) / 256, 256>>>(w1);
    convert_w2s_kernel<<<((size_t)NEXP * FDIM * HDIM / 4) / 256, 256>>>(w2);

    gemm_tc<true ><<<dim3(2 * FDIM / BN, MTILES_MAX, NEXP), 256, SMEM_TOTAL>>>(out);
    gemm_tc<false><<<dim3(HDIM / BN,     MTILES_MAX, NEXP), 256, SMEM_TOTAL>>>(out);
}

// round 4
// speedup vs baseline: 3.4323x; 1.4408x over previous
#include <cuda_runtime.h>
#include <cuda_fp16.h>
#include <cstdint>
#include <math.h>

// Problem constants
#define T_TOK 4096
#define HDIM  2048
#define FDIM  4096
#define NEXP  8
#define TOPK  2
#define NASSIGN (T_TOK * TOPK)   // 8192

// GEMM tiling (sm80-style HMMA pipeline)
#define BM 128
#define BN 256
#define BK 32
#define MTILES_MAX 16            // covers up to 2048 rows/expert

#define A_ROW_B 80               // 32 fp16 = 64B + 16B pad (conflict-free ldmatrix)
#define B_ROW_B 528              // 256 fp16 = 512B + 16B pad
#define OFF_AHI 0
#define OFF_ALO (BM * A_ROW_B)               // 10240
#define OFF_BHI (2 * BM * A_ROW_B)           // 20480
#define STAGE_B (OFF_BHI + BK * B_ROW_B)     // 37376
#define NSTAGE 4
#define SMEM_TOTAL (NSTAGE * STAGE_B)        // 149504

// ---------------------------------------------------------------------------
// Scratch (__device__ globals — no allocation anywhere)
// ---------------------------------------------------------------------------
__device__ __half g_xhi[(size_t)T_TOK * HDIM];
__device__ __half g_xlo[(size_t)T_TOK * HDIM];
// w1 hi-only, column-interleaved: [E][H][2F], col n' = 2f -> a_f, 2f+1 -> b_f
__device__ __half g_w1i[(size_t)NEXP * HDIM * 2 * FDIM];
// w2 hi-only, natural layout [E][F][H]
__device__ __half g_w2s[(size_t)NEXP * FDIM * HDIM];
// swiglu output (split fp16): [NASSIGN][F]
__device__ __half g_s_hi[(size_t)NASSIGN * FDIM];
__device__ __half g_s_lo[(size_t)NASSIGN * FDIM];

__device__ int   g_eid[T_TOK * TOPK];
__device__ float g_wt [T_TOK * TOPK];
__device__ int   g_tok[NASSIGN];
__device__ float g_w  [NASSIGN];
__device__ int   g_cnt [NEXP];
__device__ int   g_off [NEXP + 1];
__device__ int   g_fill[NEXP];

// ---------------------------------------------------------------------------
// PTX helpers (base ISA only — valid on plain sm_103 target)
// ---------------------------------------------------------------------------
__device__ __forceinline__ void cp16(uint32_t dst, const void* src, uint32_t sz) {
    asm volatile("cp.async.cg.shared.global [%0], [%1], 16, %2;"
                 :: "r"(dst), "l"(src), "r"(sz) : "memory");
}
__device__ __forceinline__ void cp_commit() {
    asm volatile("cp.async.commit_group;" ::: "memory");
}
__device__ __forceinline__ void cp_wait2() {
    asm volatile("cp.async.wait_group 2;" ::: "memory");
}
__device__ __forceinline__ void cp_wait0() {
    asm volatile("cp.async.wait_group 0;" ::: "memory");
}
__device__ __forceinline__ void ldsm4(uint32_t* r, uint32_t a) {
    asm volatile("ldmatrix.sync.aligned.m8n8.x4.shared.b16 {%0,%1,%2,%3}, [%4];"
                 : "=r"(r[0]), "=r"(r[1]), "=r"(r[2]), "=r"(r[3]) : "r"(a));
}
__device__ __forceinline__ void ldsm4t(uint32_t* r, uint32_t a) {
    asm volatile("ldmatrix.sync.aligned.m8n8.x4.trans.shared.b16 {%0,%1,%2,%3}, [%4];"
                 : "=r"(r[0]), "=r"(r[1]), "=r"(r[2]), "=r"(r[3]) : "r"(a));
}
__device__ __forceinline__ void mma4(float* c, const uint32_t* a, uint32_t b0, uint32_t b1) {
    asm volatile("mma.sync.aligned.m16n8k16.row.col.f32.f16.f16.f32 "
                 "{%0,%1,%2,%3}, {%4,%5,%6,%7}, {%8,%9}, {%0,%1,%2,%3};"
                 : "+f"(c[0]), "+f"(c[1]), "+f"(c[2]), "+f"(c[3])
                 : "r"(a[0]), "r"(a[1]), "r"(a[2]), "r"(a[3]), "r"(b0), "r"(b1));
}

__device__ __forceinline__ void split_fp16(float v, __half& h, __half& l) {
    h = __float2half_rn(v);
    l = __float2half_rn(v - __half2float(h));
}

// ---------------------------------------------------------------------------
// 0) reset output + counters
// ---------------------------------------------------------------------------
__global__ void reset_kernel(float* __restrict__ out) {
    size_t i = (size_t)blockIdx.x * blockDim.x + threadIdx.x;
    out[i] = 0.0f;  // grid sized exactly T_TOK*HDIM
    if (blockIdx.x == 0 && threadIdx.x < NEXP) g_cnt[threadIdx.x] = 0;
}

// ---------------------------------------------------------------------------
// 1) gate: top-2 + softmax (fp32, exact routing — proven)
// ---------------------------------------------------------------------------
__global__ void gate_kernel(const float* __restrict__ x, const float* __restrict__ gw) {
    int warp = threadIdx.x >> 5, lane = threadIdx.x & 31;
    int t = blockIdx.x * (blockDim.x >> 5) + warp;
    if (t >= T_TOK) return;
    float acc[NEXP];
#pragma unroll
    for (int e = 0; e < NEXP; e++) acc[e] = 0.0f;
    const float* xp = x + (size_t)t * HDIM;
    for (int h = lane; h < HDIM; h += 32) {
        float xv = xp[h];
#pragma unroll
        for (int e = 0; e < NEXP; e++) acc[e] += xv * gw[e * HDIM + h];
    }
#pragma unroll
    for (int e = 0; e < NEXP; e++)
#pragma unroll
        for (int o = 16; o > 0; o >>= 1)
            acc[e] += __shfl_xor_sync(0xffffffffu, acc[e], o);
    if (lane == 0) {
        int e0 = 0; float l0 = acc[0];
#pragma unroll
        for (int e = 1; e < NEXP; e++) if (acc[e] > l0) { l0 = acc[e]; e0 = e; }
        int e1 = -1; float l1 = -INFINITY;
#pragma unroll
        for (int e = 0; e < NEXP; e++) if (e != e0 && acc[e] > l1) { l1 = acc[e]; e1 = e; }
        float p = expf(l1 - l0);
        float s = 1.0f / (1.0f + p);
        g_eid[2 * t] = e0;  g_eid[2 * t + 1] = e1;
        g_wt [2 * t] = s;   g_wt [2 * t + 1] = p * s;
        atomicAdd(&g_cnt[e0], 1);
        atomicAdd(&g_cnt[e1], 1);
    }
}

__global__ void scan_kernel() {
    int s = 0;
    for (int e = 0; e < NEXP; e++) { g_off[e] = s; s += g_cnt[e]; g_fill[e] = 0; }
    g_off[NEXP] = s;
}

__global__ void scatter_kernel() {
    int t = blockIdx.x * blockDim.x + threadIdx.x;
    if (t >= T_TOK) return;
#pragma unroll
    for (int k = 0; k < TOPK; k++) {
        int e = g_eid[2 * t + k];
        int pos = g_off[e] + atomicAdd(&g_fill[e], 1);
        g_tok[pos] = t;
        g_w[pos]   = g_wt[2 * t + k];
    }
}

// ---------------------------------------------------------------------------
// 2) conversions
// ---------------------------------------------------------------------------
// x: fp32 -> fp16 hi + lo (8 elems / thread, 16B stores)
__global__ void convert_x_kernel(const float* __restrict__ x) {
    size_t i = ((size_t)blockIdx.x * blockDim.x + threadIdx.x) * 8;
    float4 v0 = *reinterpret_cast<const float4*>(x + i);
    float4 v1 = *reinterpret_cast<const float4*>(x + i + 4);
    __half h[8], l[8];
    split_fp16(v0.x, h[0], l[0]); split_fp16(v0.y, h[1], l[1]);
    split_fp16(v0.z, h[2], l[2]); split_fp16(v0.w, h[3], l[3]);
    split_fp16(v1.x, h[4], l[4]); split_fp16(v1.y, h[5], l[5]);
    split_fp16(v1.z, h[6], l[6]); split_fp16(v1.w, h[7], l[7]);
    *reinterpret_cast<uint4*>(g_xhi + i) = *reinterpret_cast<uint4*>(h);
    *reinterpret_cast<uint4*>(g_xlo + i) = *reinterpret_cast<uint4*>(l);
}

// w1 [E][H][2F]: interleave a/b columns -> hi fp16 only
__global__ void convert_w1i_kernel(const float* __restrict__ w1) {
    size_t i = (size_t)blockIdx.x * blockDim.x + threadIdx.x; // over E*H*(F/4)
    size_t ek = i / (FDIM / 4);
    int f0 = (int)(i % (FDIM / 4)) * 4;
    const float* src = w1 + ek * (size_t)(2 * FDIM);
    float4 va = *reinterpret_cast<const float4*>(src + f0);
    float4 vb = *reinterpret_cast<const float4*>(src + FDIM + f0);
    __half h[8];
    h[0] = __float2half_rn(va.x); h[1] = __float2half_rn(vb.x);
    h[2] = __float2half_rn(va.y); h[3] = __float2half_rn(vb.y);
    h[4] = __float2half_rn(va.z); h[5] = __float2half_rn(vb.z);
    h[6] = __float2half_rn(va.w); h[7] = __float2half_rn(vb.w);
    size_t o = ek * (size_t)(2 * FDIM) + 2 * f0;
    *reinterpret_cast<uint4*>(g_w1i + o) = *reinterpret_cast<uint4*>(h);
}

// w2 [E][F][H]: elementwise fp16 hi only (8 elems / thread)
__global__ void convert_w2s_kernel(const float* __restrict__ w2) {
    size_t i = ((size_t)blockIdx.x * blockDim.x + threadIdx.x) * 8;
    float4 v0 = *reinterpret_cast<const float4*>(w2 + i);
    float4 v1 = *reinterpret_cast<const float4*>(w2 + i + 4);
    __half h[8];
    h[0] = __float2half_rn(v0.x); h[1] = __float2half_rn(v0.y);
    h[2] = __float2half_rn(v0.z); h[3] = __float2half_rn(v0.w);
    h[4] = __float2half_rn(v1.x); h[5] = __float2half_rn(v1.y);
    h[6] = __float2half_rn(v1.z); h[7] = __float2half_rn(v1.w);
    *reinterpret_cast<uint4*>(g_w2s + i) = *reinterpret_cast<uint4*>(h);
}

// ---------------------------------------------------------------------------
// 3) grouped HMMA GEMM, 2-term fp16 split (A hi+lo, B hi), 4-stage cp.async.
//    G1=true : D = gather(x) @ w1i, fused swiglu -> g_s (split fp16)
//    G1=false: Y = S @ w2,        weighted atomic scatter -> out
// ---------------------------------------------------------------------------
template<bool G1>
__global__ __launch_bounds__(256, 1) void gemm_tc(float* __restrict__ out) {
    constexpr int KDIM = G1 ? HDIM : FDIM;
    constexpr int NCH  = KDIM / BK;
    constexpr int LDB  = G1 ? (2 * FDIM) : HDIM;

    const int tid = threadIdx.x;
    const int e = blockIdx.z;
    const int row0 = g_off[e];
    const int nrows = g_off[e + 1] - row0;
    const int mbase = blockIdx.y * BM;
    if (mbase >= nrows) return;
    const int nbase = blockIdx.x * BN;

    extern __shared__ __align__(128) char dsm[];
    const uint32_t smem0 = (uint32_t)__cvta_generic_to_shared(dsm);

    // ---- loader setup ----
    const __half *ahi[2], *alo[2];
    uint32_t adst[2], asz[2];
#pragma unroll
    for (int r = 0; r < 2; r++) {
        int idx = tid + 256 * r;
        int m = idx >> 2, cq = idx & 3;
        int gm = mbase + m;
        bool ok = gm < nrows;
        int rowid = ok ? (row0 + gm) : 0;
        if (G1) {
            int tok = ok ? g_tok[rowid] : 0;
            ahi[r] = g_xhi + (size_t)tok * HDIM + cq * 8;
            alo[r] = g_xlo + (size_t)tok * HDIM + cq * 8;
        } else {
            ahi[r] = g_s_hi + (size_t)rowid * FDIM + cq * 8;
            alo[r] = g_s_lo + (size_t)rowid * FDIM + cq * 8;
        }
        adst[r] = (uint32_t)(m * A_ROW_B + cq * 16);
        asz[r] = ok ? 16u : 0u;
    }
    const __half* bhi[4];
    uint32_t bdst[4];
#pragma unroll
    for (int j = 0; j < 4; j++) {
        int idx = tid + 256 * j;
        int row = idx >> 5, cq = idx & 31;
        size_t o;
        if (G1) o = ((size_t)e * HDIM + row) * (size_t)(2 * FDIM) + nbase + cq * 8;
        else    o = ((size_t)e * FDIM + row) * (size_t)HDIM + nbase + cq * 8;
        bhi[j] = (G1 ? g_w1i : g_w2s) + o;
        bdst[j] = (uint32_t)(row * B_ROW_B + cq * 16);
    }

    auto load_stage = [&](int ck) {
        uint32_t sb = smem0 + (ck % NSTAGE) * STAGE_B;
        size_t ka = (size_t)ck * BK;
        size_t kb = (size_t)ck * BK * LDB;
#pragma unroll
        for (int r = 0; r < 2; r++) {
            cp16(sb + OFF_AHI + adst[r], ahi[r] + ka, asz[r]);
            cp16(sb + OFF_ALO + adst[r], alo[r] + ka, asz[r]);
        }
#pragma unroll
        for (int j = 0; j < 4; j++)
            cp16(sb + OFF_BHI + bdst[j], bhi[j] + kb, 16u);
    };

    float c[4][8][4];
#pragma unroll
    for (int i = 0; i < 4; i++)
#pragma unroll
        for (int j = 0; j < 8; j++)
#pragma unroll
            for (int q = 0; q < 4; q++) c[i][j][q] = 0.0f;

    const int lane = tid & 31, wid = tid >> 5;
    const int wm = wid >> 2, wn = wid & 3;
    const int lr = lane & 15, lc = lane >> 4;

    load_stage(0); cp_commit();
    load_stage(1); cp_commit();
    load_stage(2); cp_commit();

    for (int ck = 0; ck < NCH; ck++) {
        cp_wait2();
        __syncthreads();
        if (ck + 3 < NCH) load_stage(ck + 3);
        cp_commit();

        uint32_t sb = smem0 + (ck % NSTAGE) * STAGE_B;
#pragma unroll
        for (int ko = 0; ko < 2; ko++) {
            uint32_t aAh = sb + OFF_AHI + (wm * 64 + lr) * A_ROW_B + ko * 32 + lc * 16;
            uint32_t aAl = sb + OFF_ALO + (wm * 64 + lr) * A_ROW_B + ko * 32 + lc * 16;
            uint32_t aBh = sb + OFF_BHI + (ko * 16 + lr) * B_ROW_B + wn * 128 + lc * 16;
            uint32_t a[4][4], b[4][4];
            // B fragments loaded once, reused by both terms
#pragma unroll
            for (int nj = 0; nj < 4; nj++) ldsm4t(b[nj], aBh + nj * 32);
            // term 1: Ahi x Bhi
#pragma unroll
            for (int mi = 0; mi < 4; mi++) ldsm4(a[mi], aAh + mi * 16 * A_ROW_B);
#pragma unroll
            for (int mi = 0; mi < 4; mi++)
#pragma unroll
                for (int nj = 0; nj < 4; nj++) {
                    mma4(c[mi][2 * nj],     a[mi], b[nj][0], b[nj][1]);
                    mma4(c[mi][2 * nj + 1], a[mi], b[nj][2], b[nj][3]);
                }
            // term 2: Alo x Bhi (B regs reused)
#pragma unroll
            for (int mi = 0; mi < 4; mi++) ldsm4(a[mi], aAl + mi * 16 * A_ROW_B);
#pragma unroll
            for (int mi = 0; mi < 4; mi++)
#pragma unroll
                for (int nj = 0; nj < 4; nj++) {
                    mma4(c[mi][2 * nj],     a[mi], b[nj][0], b[nj][1]);
                    mma4(c[mi][2 * nj + 1], a[mi], b[nj][2], b[nj][3]);
                }
        }
    }
    cp_wait0();

    // ---- epilogue ----
    if constexpr (G1) {
        // interleaved (a,b) column pairs: swiglu is thread-local
#pragma unroll
        for (int mi = 0; mi < 4; mi++) {
            int r0 = wm * 64 + mi * 16 + (lane >> 2);
            int gm0 = mbase + r0, gm1 = gm0 + 8;
            bool ok0 = gm0 < nrows, ok1 = gm1 < nrows;
            size_t s0 = (size_t)(row0 + gm0) * FDIM;
            size_t s1 = (size_t)(row0 + gm1) * FDIM;
#pragma unroll
            for (int n8 = 0; n8 < 8; n8++) {
                int f = (nbase >> 1) + wn * 32 + n8 * 4 + (lane & 3);
                if (ok0) {
                    float a = c[mi][n8][0], bb = c[mi][n8][1];
                    float sv = a / (1.0f + expf(-a)) * bb;
                    __half h, l; split_fp16(sv, h, l);
                    g_s_hi[s0 + f] = h; g_s_lo[s0 + f] = l;
                }
                if (ok1) {
                    float a = c[mi][n8][2], bb = c[mi][n8][3];
                    float sv = a / (1.0f + expf(-a)) * bb;
                    __half h, l; split_fp16(sv, h, l);
                    g_s_hi[s1 + f] = h; g_s_lo[s1 + f] = l;
                }
            }
        }
    } else {
#pragma unroll
        for (int mi = 0; mi < 4; mi++) {
            int r0 = wm * 64 + mi * 16 + (lane >> 2);
            int gm0 = mbase + r0, gm1 = gm0 + 8;
            bool ok0 = gm0 < nrows, ok1 = gm1 < nrows;
            int tok0 = ok0 ? g_tok[row0 + gm0] : 0;
            int tok1 = ok1 ? g_tok[row0 + gm1] : 0;
            float w0 = ok0 ? g_w[row0 + gm0] : 0.0f;
            float w1v = ok1 ? g_w[row0 + gm1] : 0.0f;
            float* o0 = out + (size_t)tok0 * HDIM;
            float* o1 = out + (size_t)tok1 * HDIM;
#pragma unroll
            for (int n8 = 0; n8 < 8; n8++) {
                int col = nbase + wn * 64 + n8 * 8 + (lane & 3) * 2;
                if (ok0) {
                    atomicAdd(o0 + col,     w0 * c[mi][n8][0]);
                    atomicAdd(o0 + col + 1, w0 * c[mi][n8][1]);
                }
                if (ok1) {
                    atomicAdd(o1 + col,     w1v * c[mi][n8][2]);
                    atomicAdd(o1 + col + 1, w1v * c[mi][n8][3]);
                }
            }
        }
    }
}

// ---------------------------------------------------------------------------
// launch
// ---------------------------------------------------------------------------
extern "C" void kernel_launch(void* const* d_in, const int* in_sizes, int n_in,
                              void* d_out, int out_size) {
    const float* x  = (const float*)d_in[0]; // [T, H]
    const float* gw = (const float*)d_in[1]; // [E, H]
    const float* w1 = (const float*)d_in[2]; // [E, H, 2F]
    const float* w2 = (const float*)d_in[3]; // [E, F, H]
    float* out = (float*)d_out;              // [T, H]

    cudaFuncSetAttribute(gemm_tc<true>,  cudaFuncAttributeMaxDynamicSharedMemorySize, SMEM_TOTAL);
    cudaFuncSetAttribute(gemm_tc<false>, cudaFuncAttributeMaxDynamicSharedMemorySize, SMEM_TOTAL);

    reset_kernel<<<8192, 1024>>>(out);                     // T*H exactly
    gate_kernel<<<T_TOK / 8, 256>>>(x, gw);
    scan_kernel<<<1, 1>>>();
    scatter_kernel<<<T_TOK / 256, 256>>>();

    convert_x_kernel<<<(T_TOK * HDIM / 8) / 256, 256>>>(x);
    convert_w1i_kernel<<<(NEXP * HDIM * (FDIM / 4)) / 256, 256>>>(w1);
    convert_w2s_kernel<<<(int)(((size_t)NEXP * FDIM * HDIM / 8) / 256), 256>>>(w2);

    gemm_tc<true ><<<dim3(2 * FDIM / BN, MTILES_MAX, NEXP), 256, SMEM_TOTAL>>>(out);
    gemm_tc<false><<<dim3(HDIM / BN,     MTILES_MAX, NEXP), 256, SMEM_TOTAL>>>(out);
}

// round 5
// speedup vs baseline: 5.7517x; 1.6757x over previous
#include <cuda_runtime.h>
#include <cuda_fp16.h>
#include <cstdint>
#include <math.h>

// Problem constants
#define T_TOK 4096
#define HDIM  2048
#define FDIM  4096
#define NEXP  8
#define TOPK  2
#define NASSIGN (T_TOK * TOPK)   // 8192

// GEMM tiling
#define BM 128
#define BN 256
#define BK 64
#define MTILES_MAX 16

#define A_ROW_B 144              // 64 fp16 = 128B + 16B pad
#define B_ROW_B 528              // 256 fp16 = 512B + 16B pad
#define OFF_B   (BM * A_ROW_B)               // 18432
#define STAGE_B (OFF_B + BK * B_ROW_B)       // 52224
#define NSTAGE  3
#define SMEM_TOTAL (NSTAGE * STAGE_B)        // 156672
#define EP_STRIDE_B 112          // epilogue smem row stride (16B-mult, bank-spread)

// ---------------------------------------------------------------------------
// Scratch
// ---------------------------------------------------------------------------
__device__ __half g_x[(size_t)T_TOK * HDIM];
// w1 fp16, column-interleaved: [E][H][2F], col n' = 2f -> a_f, 2f+1 -> b_f
__device__ __half g_w1i[(size_t)NEXP * HDIM * 2 * FDIM];
// w2 fp16, natural layout [E][F][H]
__device__ __half g_w2s[(size_t)NEXP * FDIM * HDIM];
// swiglu output fp16: [NASSIGN][F]
__device__ __half g_s[(size_t)NASSIGN * FDIM];

__device__ int   g_eid[T_TOK * TOPK];
__device__ float g_wt [T_TOK * TOPK];
__device__ int   g_tok[NASSIGN];
__device__ float g_w  [NASSIGN];
__device__ int   g_cnt [NEXP];
__device__ int   g_off [NEXP + 1];
__device__ int   g_fill[NEXP];

// ---------------------------------------------------------------------------
// PTX helpers (base ISA only — valid on plain sm_103 target)
// ---------------------------------------------------------------------------
__device__ __forceinline__ void cp16(uint32_t dst, const void* src, uint32_t sz) {
    asm volatile("cp.async.cg.shared.global [%0], [%1], 16, %2;"
                 :: "r"(dst), "l"(src), "r"(sz) : "memory");
}
__device__ __forceinline__ void cp_commit() {
    asm volatile("cp.async.commit_group;" ::: "memory");
}
__device__ __forceinline__ void cp_wait1() {
    asm volatile("cp.async.wait_group 1;" ::: "memory");
}
__device__ __forceinline__ void cp_wait0() {
    asm volatile("cp.async.wait_group 0;" ::: "memory");
}
__device__ __forceinline__ void ldsm4(uint32_t* r, uint32_t a) {
    asm volatile("ldmatrix.sync.aligned.m8n8.x4.shared.b16 {%0,%1,%2,%3}, [%4];"
                 : "=r"(r[0]), "=r"(r[1]), "=r"(r[2]), "=r"(r[3]) : "r"(a));
}
__device__ __forceinline__ void ldsm4t(uint32_t* r, uint32_t a) {
    asm volatile("ldmatrix.sync.aligned.m8n8.x4.trans.shared.b16 {%0,%1,%2,%3}, [%4];"
                 : "=r"(r[0]), "=r"(r[1]), "=r"(r[2]), "=r"(r[3]) : "r"(a));
}
__device__ __forceinline__ void mma4(float* c, const uint32_t* a, uint32_t b0, uint32_t b1) {
    asm volatile("mma.sync.aligned.m16n8k16.row.col.f32.f16.f16.f32 "
                 "{%0,%1,%2,%3}, {%4,%5,%6,%7}, {%8,%9}, {%0,%1,%2,%3};"
                 : "+f"(c[0]), "+f"(c[1]), "+f"(c[2]), "+f"(c[3])
                 : "r"(a[0]), "r"(a[1]), "r"(a[2]), "r"(a[3]), "r"(b0), "r"(b1));
}

// ---------------------------------------------------------------------------
// 0) reset output + counters
// ---------------------------------------------------------------------------
__global__ void reset_kernel(float* __restrict__ out) {
    size_t i = (size_t)blockIdx.x * blockDim.x + threadIdx.x;
    out[i] = 0.0f;  // grid sized exactly T_TOK*HDIM
    if (blockIdx.x == 0 && threadIdx.x < NEXP) g_cnt[threadIdx.x] = 0;
}

// ---------------------------------------------------------------------------
// 1) gate: top-2 + softmax in fp32 (exact routing — proven)
// ---------------------------------------------------------------------------
__global__ void gate_kernel(const float* __restrict__ x, const float* __restrict__ gw) {
    int warp = threadIdx.x >> 5, lane = threadIdx.x & 31;
    int t = blockIdx.x * (blockDim.x >> 5) + warp;
    if (t >= T_TOK) return;
    float acc[NEXP];
#pragma unroll
    for (int e = 0; e < NEXP; e++) acc[e] = 0.0f;
    const float* xp = x + (size_t)t * HDIM;
    for (int h = lane; h < HDIM; h += 32) {
        float xv = xp[h];
#pragma unroll
        for (int e = 0; e < NEXP; e++) acc[e] += xv * gw[e * HDIM + h];
    }
#pragma unroll
    for (int e = 0; e < NEXP; e++)
#pragma unroll
        for (int o = 16; o > 0; o >>= 1)
            acc[e] += __shfl_xor_sync(0xffffffffu, acc[e], o);
    if (lane == 0) {
        int e0 = 0; float l0 = acc[0];
#pragma unroll
        for (int e = 1; e < NEXP; e++) if (acc[e] > l0) { l0 = acc[e]; e0 = e; }
        int e1 = -1; float l1 = -INFINITY;
#pragma unroll
        for (int e = 0; e < NEXP; e++) if (e != e0 && acc[e] > l1) { l1 = acc[e]; e1 = e; }
        float p = expf(l1 - l0);
        float s = 1.0f / (1.0f + p);
        g_eid[2 * t] = e0;  g_eid[2 * t + 1] = e1;
        g_wt [2 * t] = s;   g_wt [2 * t + 1] = p * s;
        atomicAdd(&g_cnt[e0], 1);
        atomicAdd(&g_cnt[e1], 1);
    }
}

__global__ void scan_kernel() {
    int s = 0;
    for (int e = 0; e < NEXP; e++) { g_off[e] = s; s += g_cnt[e]; g_fill[e] = 0; }
    g_off[NEXP] = s;
}

__global__ void scatter_kernel() {
    int t = blockIdx.x * blockDim.x + threadIdx.x;
    if (t >= T_TOK) return;
#pragma unroll
    for (int k = 0; k < TOPK; k++) {
        int e = g_eid[2 * t + k];
        int pos = g_off[e] + atomicAdd(&g_fill[e], 1);
        g_tok[pos] = t;
        g_w[pos]   = g_wt[2 * t + k];
    }
}

// ---------------------------------------------------------------------------
// 2) conversions: fp32 -> fp16
// ---------------------------------------------------------------------------
__global__ void convert_x_kernel(const float* __restrict__ x) {
    size_t i = ((size_t)blockIdx.x * blockDim.x + threadIdx.x) * 8;
    float4 v0 = *reinterpret_cast<const float4*>(x + i);
    float4 v1 = *reinterpret_cast<const float4*>(x + i + 4);
    __half h[8];
    h[0] = __float2half_rn(v0.x); h[1] = __float2half_rn(v0.y);
    h[2] = __float2half_rn(v0.z); h[3] = __float2half_rn(v0.w);
    h[4] = __float2half_rn(v1.x); h[5] = __float2half_rn(v1.y);
    h[6] = __float2half_rn(v1.z); h[7] = __float2half_rn(v1.w);
    *reinterpret_cast<uint4*>(g_x + i) = *reinterpret_cast<uint4*>(h);
}

// w1 [E][H][2F]: interleave a/b columns -> fp16
__global__ void convert_w1i_kernel(const float* __restrict__ w1) {
    size_t i = (size_t)blockIdx.x * blockDim.x + threadIdx.x; // over E*H*(F/4)
    size_t ek = i / (FDIM / 4);
    int f0 = (int)(i % (FDIM / 4)) * 4;
    const float* src = w1 + ek * (size_t)(2 * FDIM);
    float4 va = *reinterpret_cast<const float4*>(src + f0);
    float4 vb = *reinterpret_cast<const float4*>(src + FDIM + f0);
    __half h[8];
    h[0] = __float2half_rn(va.x); h[1] = __float2half_rn(vb.x);
    h[2] = __float2half_rn(va.y); h[3] = __float2half_rn(vb.y);
    h[4] = __float2half_rn(va.z); h[5] = __float2half_rn(vb.z);
    h[6] = __float2half_rn(va.w); h[7] = __float2half_rn(vb.w);
    size_t o = ek * (size_t)(2 * FDIM) + 2 * f0;
    *reinterpret_cast<uint4*>(g_w1i + o) = *reinterpret_cast<uint4*>(h);
}

// w2 [E][F][H]: elementwise fp16
__global__ void convert_w2s_kernel(const float* __restrict__ w2) {
    size_t i = ((size_t)blockIdx.x * blockDim.x + threadIdx.x) * 8;
    float4 v0 = *reinterpret_cast<const float4*>(w2 + i);
    float4 v1 = *reinterpret_cast<const float4*>(w2 + i + 4);
    __half h[8];
    h[0] = __float2half_rn(v0.x); h[1] = __float2half_rn(v0.y);
    h[2] = __float2half_rn(v0.z); h[3] = __float2half_rn(v0.w);
    h[4] = __float2half_rn(v1.x); h[5] = __float2half_rn(v1.y);
    h[6] = __float2half_rn(v1.z); h[7] = __float2half_rn(v1.w);
    *reinterpret_cast<uint4*>(g_w2s + i) = *reinterpret_cast<uint4*>(h);
}

// ---------------------------------------------------------------------------
// 3) grouped HMMA GEMM, single fp16 term, BK=64, 3-stage cp.async.
//    G1=true : D = gather(x) @ w1i, fused swiglu -> g_s (fp16, vectorized)
//    G1=false: Y = S @ w2,          weighted atomic scatter -> out
// ---------------------------------------------------------------------------
template<bool G1>
__global__ __launch_bounds__(256, 1) void gemm_tc(float* __restrict__ out) {
    constexpr int KDIM = G1 ? HDIM : FDIM;
    constexpr int NCH  = KDIM / BK;
    constexpr int LDB  = G1 ? (2 * FDIM) : HDIM;

    const int tid = threadIdx.x;
    const int e = blockIdx.z;
    const int row0 = g_off[e];
    const int nrows = g_off[e + 1] - row0;
    const int mbase = blockIdx.y * BM;
    if (mbase >= nrows) return;
    const int nbase = blockIdx.x * BN;

    extern __shared__ __align__(128) char dsm[];
    const uint32_t smem0 = (uint32_t)__cvta_generic_to_shared(dsm);

    // ---- loader setup: A = 128x64 fp16 (4 x 16B per thread) ----
    const __half* aptr[4];
    uint32_t adst[4], asz[4];
#pragma unroll
    for (int r = 0; r < 4; r++) {
        int idx = tid + 256 * r;
        int m = idx >> 3, cq = idx & 7;
        int gm = mbase + m;
        bool ok = gm < nrows;
        int rowid = ok ? (row0 + gm) : 0;
        if (G1) {
            int tok = ok ? g_tok[rowid] : 0;
            aptr[r] = g_x + (size_t)tok * HDIM + cq * 8;
        } else {
            aptr[r] = g_s + (size_t)rowid * FDIM + cq * 8;
        }
        adst[r] = (uint32_t)(m * A_ROW_B + cq * 16);
        asz[r] = ok ? 16u : 0u;
    }
    // B = 64x256 fp16 (8 x 16B per thread)
    const __half* bptr[8];
    uint32_t bdst[8];
#pragma unroll
    for (int j = 0; j < 8; j++) {
        int idx = tid + 256 * j;
        int row = idx >> 5, cq = idx & 31;
        size_t o;
        if (G1) o = ((size_t)e * HDIM + row) * (size_t)(2 * FDIM) + nbase + cq * 8;
        else    o = ((size_t)e * FDIM + row) * (size_t)HDIM + nbase + cq * 8;
        bptr[j] = (G1 ? g_w1i : g_w2s) + o;
        bdst[j] = (uint32_t)(OFF_B + row * B_ROW_B + cq * 16);
    }

    auto load_stage = [&](int ck) {
        uint32_t sb = smem0 + (ck % NSTAGE) * STAGE_B;
        size_t ka = (size_t)ck * BK;
        size_t kb = (size_t)ck * BK * LDB;
#pragma unroll
        for (int r = 0; r < 4; r++)
            cp16(sb + adst[r], aptr[r] + ka, asz[r]);
#pragma unroll
        for (int j = 0; j < 8; j++)
            cp16(sb + bdst[j], bptr[j] + kb, 16u);
    };

    float c[4][8][4];
#pragma unroll
    for (int i = 0; i < 4; i++)
#pragma unroll
        for (int j = 0; j < 8; j++)
#pragma unroll
            for (int q = 0; q < 4; q++) c[i][j][q] = 0.0f;

    const int lane = tid & 31, wid = tid >> 5;
    const int wm = wid >> 2, wn = wid & 3;
    const int lr = lane & 15, lc = lane >> 4;

    load_stage(0); cp_commit();
    load_stage(1); cp_commit();

    for (int ck = 0; ck < NCH; ck++) {
        cp_wait1();
        __syncthreads();
        if (ck + 2 < NCH) load_stage(ck + 2);
        cp_commit();

        uint32_t sb = smem0 + (ck % NSTAGE) * STAGE_B;
#pragma unroll
        for (int ko = 0; ko < 4; ko++) {
            uint32_t aA = sb + (wm * 64 + lr) * A_ROW_B + ko * 32 + lc * 16;
            uint32_t aB = sb + OFF_B + (ko * 16 + lr) * B_ROW_B + wn * 128 + lc * 16;
            uint32_t a[4][4], b[4][4];
#pragma unroll
            for (int nj = 0; nj < 4; nj++) ldsm4t(b[nj], aB + nj * 32);
#pragma unroll
            for (int mi = 0; mi < 4; mi++) ldsm4(a[mi], aA + mi * 16 * A_ROW_B);
#pragma unroll
            for (int mi = 0; mi < 4; mi++)
#pragma unroll
                for (int nj = 0; nj < 4; nj++) {
                    mma4(c[mi][2 * nj],     a[mi], b[nj][0], b[nj][1]);
                    mma4(c[mi][2 * nj + 1], a[mi], b[nj][2], b[nj][3]);
                }
        }
    }
    cp_wait0();
    __syncthreads();   // all compute done -> smem reusable for epilogue staging

    // ---- epilogue ----
    if constexpr (G1) {
        // swiglu on interleaved (a,b) pairs, stage through smem, vector stores
        __half* ep = reinterpret_cast<__half*>(dsm + wid * 64 * EP_STRIDE_B);
        const int q = lane & 3, lrow = lane >> 2;
#pragma unroll
        for (int mi = 0; mi < 4; mi++) {
            int r0 = mi * 16 + lrow;
#pragma unroll
            for (int n8 = 0; n8 < 8; n8++) {
                int col = n8 * 4 + q;
                float a0 = c[mi][n8][0], b0 = c[mi][n8][1];
                float a1 = c[mi][n8][2], b1 = c[mi][n8][3];
                float s0 = a0 / (1.0f + expf(-a0)) * b0;
                float s1 = a1 / (1.0f + expf(-a1)) * b1;
                *reinterpret_cast<__half*>(
                    reinterpret_cast<char*>(ep) + r0 * EP_STRIDE_B + col * 2) =
                    __float2half_rn(s0);
                *reinterpret_cast<__half*>(
                    reinterpret_cast<char*>(ep) + (r0 + 8) * EP_STRIDE_B + col * 2) =
                    __float2half_rn(s1);
            }
        }
        __syncwarp();
        const int fb = (nbase >> 1) + wn * 32;
#pragma unroll
        for (int j = 0; j < 8; j++) {
            int row = j * 8 + lrow;
            int gm = mbase + wm * 64 + row;
            if (gm < nrows) {
                uint4 v = *reinterpret_cast<const uint4*>(
                    reinterpret_cast<char*>(ep) + row * EP_STRIDE_B + q * 16);
                *reinterpret_cast<uint4*>(
                    &g_s[(size_t)(row0 + gm) * FDIM + fb + q * 8]) = v;
            }
        }
    } else {
        const int q = lane & 3, lrow = lane >> 2;
#pragma unroll
        for (int mi = 0; mi < 4; mi++) {
            int r0 = wm * 64 + mi * 16 + lrow;
            int gm0 = mbase + r0, gm1 = gm0 + 8;
            bool ok0 = gm0 < nrows, ok1 = gm1 < nrows;
            int tok0 = ok0 ? g_tok[row0 + gm0] : 0;
            int tok1 = ok1 ? g_tok[row0 + gm1] : 0;
            float w0 = ok0 ? g_w[row0 + gm0] : 0.0f;
            float w1v = ok1 ? g_w[row0 + gm1] : 0.0f;
            float* o0 = out + (size_t)tok0 * HDIM;
            float* o1 = out + (size_t)tok1 * HDIM;
#pragma unroll
            for (int n8 = 0; n8 < 8; n8++) {
                int col = nbase + wn * 64 + n8 * 8 + q * 2;
                if (ok0) {
                    atomicAdd(o0 + col,     w0 * c[mi][n8][0]);
                    atomicAdd(o0 + col + 1, w0 * c[mi][n8][1]);
                }
                if (ok1) {
                    atomicAdd(o1 + col,     w1v * c[mi][n8][2]);
                    atomicAdd(o1 + col + 1, w1v * c[mi][n8][3]);
                }
            }
        }
    }
}

// ---------------------------------------------------------------------------
// launch
// ---------------------------------------------------------------------------
extern "C" void kernel_launch(void* const* d_in, const int* in_sizes, int n_in,
                              void* d_out, int out_size) {
    const float* x  = (const float*)d_in[0]; // [T, H]
    const float* gw = (const float*)d_in[1]; // [E, H]
    const float* w1 = (const float*)d_in[2]; // [E, H, 2F]
    const float* w2 = (const float*)d_in[3]; // [E, F, H]
    float* out = (float*)d_out;              // [T, H]

    cudaFuncSetAttribute(gemm_tc<true>,  cudaFuncAttributeMaxDynamicSharedMemorySize, SMEM_TOTAL);
    cudaFuncSetAttribute(gemm_tc<false>, cudaFuncAttributeMaxDynamicSharedMemorySize, SMEM_TOTAL);

    reset_kernel<<<8192, 1024>>>(out);                     // T*H exactly
    gate_kernel<<<T_TOK / 8, 256>>>(x, gw);
    scan_kernel<<<1, 1>>>();
    scatter_kernel<<<T_TOK / 256, 256>>>();

    convert_x_kernel<<<(T_TOK * HDIM / 8) / 256, 256>>>(x);
    convert_w1i_kernel<<<(NEXP * HDIM * (FDIM / 4)) / 256, 256>>>(w1);
    convert_w2s_kernel<<<(int)(((size_t)NEXP * FDIM * HDIM / 8) / 256), 256>>>(w2);

    gemm_tc<true ><<<dim3(2 * FDIM / BN, MTILES_MAX, NEXP), 256, SMEM_TOTAL>>>(out);
    gemm_tc<false><<<dim3(HDIM / BN,     MTILES_MAX, NEXP), 256, SMEM_TOTAL>>>(out);
}

// round 6
// speedup vs baseline: 5.7822x; 1.0053x over previous
#include <cuda_runtime.h>
#include <cuda_fp16.h>
#include <cstdint>
#include <math.h>

// Problem constants
#define T_TOK 4096
#define HDIM  2048
#define FDIM  4096
#define NEXP  8
#define TOPK  2
#define NASSIGN (T_TOK * TOPK)   // 8192

// GEMM tiling
#define BM 128
#define BN 256
#define BK 64
#define MTILES_MAX 16

#define A_ROW_B 144              // 64 fp16 = 128B + 16B pad
#define B_ROW_B 528              // 256 fp16 = 512B + 16B pad
#define OFF_B   (BM * A_ROW_B)               // 18432
#define STAGE_B (OFF_B + BK * B_ROW_B)       // 52224
#define NSTAGE  3
#define SMEM_TOTAL (NSTAGE * STAGE_B)        // 156672
#define EP_STRIDE_B 112          // epilogue smem row stride

// ---------------------------------------------------------------------------
// Scratch
// ---------------------------------------------------------------------------
__device__ __half g_x[(size_t)T_TOK * HDIM];
// w1 fp16, column-interleaved: [E][H][2F], col n' = 2f -> a_f, 2f+1 -> b_f
__device__ __half g_w1i[(size_t)NEXP * HDIM * 2 * FDIM];
// w2 fp16, natural layout [E][F][H]
__device__ __half g_w2s[(size_t)NEXP * FDIM * HDIM];
// swiglu output fp16: [NASSIGN][F]
__device__ __half g_s[(size_t)NASSIGN * FDIM];

__device__ int   g_eid[T_TOK * TOPK];
__device__ float g_wt [T_TOK * TOPK];
__device__ int   g_tok[NASSIGN];
__device__ float g_w  [NASSIGN];
__device__ int   g_cnt [NEXP];
__device__ int   g_off [NEXP + 1];
__device__ int   g_fill[NEXP];

// ---------------------------------------------------------------------------
// PTX helpers (base ISA only — valid on plain sm_103 target)
// ---------------------------------------------------------------------------
__device__ __forceinline__ void cp16(uint32_t dst, const void* src, uint32_t sz) {
    asm volatile("cp.async.cg.shared.global [%0], [%1], 16, %2;"
                 :: "r"(dst), "l"(src), "r"(sz) : "memory");
}
__device__ __forceinline__ void cp_commit() {
    asm volatile("cp.async.commit_group;" ::: "memory");
}
__device__ __forceinline__ void cp_wait1() {
    asm volatile("cp.async.wait_group 1;" ::: "memory");
}
__device__ __forceinline__ void cp_wait0() {
    asm volatile("cp.async.wait_group 0;" ::: "memory");
}
__device__ __forceinline__ void ldsm4(uint32_t* r, uint32_t a) {
    asm volatile("ldmatrix.sync.aligned.m8n8.x4.shared.b16 {%0,%1,%2,%3}, [%4];"
                 : "=r"(r[0]), "=r"(r[1]), "=r"(r[2]), "=r"(r[3]) : "r"(a));
}
__device__ __forceinline__ void ldsm4t(uint32_t* r, uint32_t a) {
    asm volatile("ldmatrix.sync.aligned.m8n8.x4.trans.shared.b16 {%0,%1,%2,%3}, [%4];"
                 : "=r"(r[0]), "=r"(r[1]), "=r"(r[2]), "=r"(r[3]) : "r"(a));
}
__device__ __forceinline__ void mma4(float* c, const uint32_t* a, uint32_t b0, uint32_t b1) {
    asm volatile("mma.sync.aligned.m16n8k16.row.col.f32.f16.f16.f32 "
                 "{%0,%1,%2,%3}, {%4,%5,%6,%7}, {%8,%9}, {%0,%1,%2,%3};"
                 : "+f"(c[0]), "+f"(c[1]), "+f"(c[2]), "+f"(c[3])
                 : "r"(a[0]), "r"(a[1]), "r"(a[2]), "r"(a[3]), "r"(b0), "r"(b1));
}

// ---------------------------------------------------------------------------
// 0) reset output (runs after routing, before gemm2 — the only consumer)
// ---------------------------------------------------------------------------
__global__ void reset_kernel(float* __restrict__ out) {
    size_t i = (size_t)blockIdx.x * blockDim.x + threadIdx.x;
    out[i] = 0.0f;  // grid sized exactly T_TOK*HDIM
}

// ---------------------------------------------------------------------------
// 1) convert x (launch #1; also zeroes expert counters for this replay)
// ---------------------------------------------------------------------------
__global__ void convert_x_kernel(const float* __restrict__ x) {
    if (blockIdx.x == 0 && threadIdx.x < NEXP) g_cnt[threadIdx.x] = 0;
    size_t i = ((size_t)blockIdx.x * blockDim.x + threadIdx.x) * 8;
    float4 v0 = *reinterpret_cast<const float4*>(x + i);
    float4 v1 = *reinterpret_cast<const float4*>(x + i + 4);
    __half h[8];
    h[0] = __float2half_rn(v0.x); h[1] = __float2half_rn(v0.y);
    h[2] = __float2half_rn(v0.z); h[3] = __float2half_rn(v0.w);
    h[4] = __float2half_rn(v1.x); h[5] = __float2half_rn(v1.y);
    h[6] = __float2half_rn(v1.z); h[7] = __float2half_rn(v1.w);
    *reinterpret_cast<uint4*>(g_x + i) = *reinterpret_cast<uint4*>(h);
}

// ---------------------------------------------------------------------------
// 2) gate: top-2 + softmax in fp32 (exact routing — proven)
// ---------------------------------------------------------------------------
__global__ void gate_kernel(const float* __restrict__ x, const float* __restrict__ gw) {
    int warp = threadIdx.x >> 5, lane = threadIdx.x & 31;
    int t = blockIdx.x * (blockDim.x >> 5) + warp;
    if (t >= T_TOK) return;
    float acc[NEXP];
#pragma unroll
    for (int e = 0; e < NEXP; e++) acc[e] = 0.0f;
    const float* xp = x + (size_t)t * HDIM;
    for (int h = lane; h < HDIM; h += 32) {
        float xv = xp[h];
#pragma unroll
        for (int e = 0; e < NEXP; e++) acc[e] += xv * gw[e * HDIM + h];
    }
#pragma unroll
    for (int e = 0; e < NEXP; e++)
#pragma unroll
        for (int o = 16; o > 0; o >>= 1)
            acc[e] += __shfl_xor_sync(0xffffffffu, acc[e], o);
    if (lane == 0) {
        int e0 = 0; float l0 = acc[0];
#pragma unroll
        for (int e = 1; e < NEXP; e++) if (acc[e] > l0) { l0 = acc[e]; e0 = e; }
        int e1 = -1; float l1 = -INFINITY;
#pragma unroll
        for (int e = 0; e < NEXP; e++) if (e != e0 && acc[e] > l1) { l1 = acc[e]; e1 = e; }
        float p = expf(l1 - l0);
        float s = 1.0f / (1.0f + p);
        g_eid[2 * t] = e0;  g_eid[2 * t + 1] = e1;
        g_wt [2 * t] = s;   g_wt [2 * t + 1] = p * s;
        atomicAdd(&g_cnt[e0], 1);
        atomicAdd(&g_cnt[e1], 1);
    }
}

__global__ void scan_kernel() {
    int s = 0;
    for (int e = 0; e < NEXP; e++) { g_off[e] = s; s += g_cnt[e]; g_fill[e] = 0; }
    g_off[NEXP] = s;
}

__global__ void scatter_kernel() {
    int t = blockIdx.x * blockDim.x + threadIdx.x;
    if (t >= T_TOK) return;
#pragma unroll
    for (int k = 0; k < TOPK; k++) {
        int e = g_eid[2 * t + k];
        int pos = g_off[e] + atomicAdd(&g_fill[e], 1);
        g_tok[pos] = t;
        g_w[pos]   = g_wt[2 * t + k];
    }
}

// ---------------------------------------------------------------------------
// 3) weight conversions: fp32 -> fp16
// ---------------------------------------------------------------------------
// w1 [E][H][2F]: interleave a/b columns -> fp16
__global__ void convert_w1i_kernel(const float* __restrict__ w1) {
    size_t i = (size_t)blockIdx.x * blockDim.x + threadIdx.x; // over E*H*(F/4)
    size_t ek = i / (FDIM / 4);
    int f0 = (int)(i % (FDIM / 4)) * 4;
    const float* src = w1 + ek * (size_t)(2 * FDIM);
    float4 va = *reinterpret_cast<const float4*>(src + f0);
    float4 vb = *reinterpret_cast<const float4*>(src + FDIM + f0);
    __half h[8];
    h[0] = __float2half_rn(va.x); h[1] = __float2half_rn(vb.x);
    h[2] = __float2half_rn(va.y); h[3] = __float2half_rn(vb.y);
    h[4] = __float2half_rn(va.z); h[5] = __float2half_rn(vb.z);
    h[6] = __float2half_rn(va.w); h[7] = __float2half_rn(vb.w);
    size_t o = ek * (size_t)(2 * FDIM) + 2 * f0;
    *reinterpret_cast<uint4*>(g_w1i + o) = *reinterpret_cast<uint4*>(h);
}

// w2 [E][F][H]: elementwise fp16
__global__ void convert_w2s_kernel(const float* __restrict__ w2) {
    size_t i = ((size_t)blockIdx.x * blockDim.x + threadIdx.x) * 8;
    float4 v0 = *reinterpret_cast<const float4*>(w2 + i);
    float4 v1 = *reinterpret_cast<const float4*>(w2 + i + 4);
    __half h[8];
    h[0] = __float2half_rn(v0.x); h[1] = __float2half_rn(v0.y);
    h[2] = __float2half_rn(v0.z); h[3] = __float2half_rn(v0.w);
    h[4] = __float2half_rn(v1.x); h[5] = __float2half_rn(v1.y);
    h[6] = __float2half_rn(v1.z); h[7] = __float2half_rn(v1.w);
    *reinterpret_cast<uint4*>(g_w2s + i) = *reinterpret_cast<uint4*>(h);
}

// ---------------------------------------------------------------------------
// 4) grouped HMMA GEMM, fp16, BK=64, 3-stage cp.async,
//    register double-buffered ldmatrix fragments across ko.
//    G1=true : D = gather(x) @ w1i, fused swiglu -> g_s (fp16, vectorized)
//    G1=false: Y = S @ w2,          weighted atomic scatter -> out
// ---------------------------------------------------------------------------
template<bool G1>
__global__ __launch_bounds__(256) void gemm_tc(float* __restrict__ out) {
    constexpr int KDIM = G1 ? HDIM : FDIM;
    constexpr int NCH  = KDIM / BK;
    constexpr int LDB  = G1 ? (2 * FDIM) : HDIM;

    const int tid = threadIdx.x;
    const int e = blockIdx.z;
    const int row0 = g_off[e];
    const int nrows = g_off[e + 1] - row0;
    const int mbase = blockIdx.y * BM;
    if (mbase >= nrows) return;
    const int nbase = blockIdx.x * BN;

    extern __shared__ __align__(128) char dsm[];
    const uint32_t smem0 = (uint32_t)__cvta_generic_to_shared(dsm);

    // ---- loader setup: A = 128x64 fp16 (4 x 16B per thread) ----
    const __half* aptr[4];
    uint32_t adst[4], asz[4];
#pragma unroll
    for (int r = 0; r < 4; r++) {
        int idx = tid + 256 * r;
        int m = idx >> 3, cq = idx & 7;
        int gm = mbase + m;
        bool ok = gm < nrows;
        int rowid = ok ? (row0 + gm) : 0;
        if (G1) {
            int tok = ok ? g_tok[rowid] : 0;
            aptr[r] = g_x + (size_t)tok * HDIM + cq * 8;
        } else {
            aptr[r] = g_s + (size_t)rowid * FDIM + cq * 8;
        }
        adst[r] = (uint32_t)(m * A_ROW_B + cq * 16);
        asz[r] = ok ? 16u : 0u;
    }
    // B = 64x256 fp16 (8 x 16B per thread)
    const __half* bptr[8];
    uint32_t bdst[8];
#pragma unroll
    for (int j = 0; j < 8; j++) {
        int idx = tid + 256 * j;
        int row = idx >> 5, cq = idx & 31;
        size_t o;
        if (G1) o = ((size_t)e * HDIM + row) * (size_t)(2 * FDIM) + nbase + cq * 8;
        else    o = ((size_t)e * FDIM + row) * (size_t)HDIM + nbase + cq * 8;
        bptr[j] = (G1 ? g_w1i : g_w2s) + o;
        bdst[j] = (uint32_t)(OFF_B + row * B_ROW_B + cq * 16);
    }

    auto load_stage = [&](int ck) {
        uint32_t sb = smem0 + (ck % NSTAGE) * STAGE_B;
        size_t ka = (size_t)ck * BK;
        size_t kb = (size_t)ck * BK * LDB;
#pragma unroll
        for (int r = 0; r < 4; r++)
            cp16(sb + adst[r], aptr[r] + ka, asz[r]);
#pragma unroll
        for (int j = 0; j < 8; j++)
            cp16(sb + bdst[j], bptr[j] + kb, 16u);
    };

    float c[4][8][4];
#pragma unroll
    for (int i = 0; i < 4; i++)
#pragma unroll
        for (int j = 0; j < 8; j++)
#pragma unroll
            for (int q = 0; q < 4; q++) c[i][j][q] = 0.0f;

    const int lane = tid & 31, wid = tid >> 5;
    const int wm = wid >> 2, wn = wid & 3;
    const int lr = lane & 15, lc = lane >> 4;

    // double-buffered fragments
    uint32_t afr[2][4][4], bfr[2][4][4];
    auto load_frags = [&](int ko, int pb, uint32_t sb) {
        uint32_t aA = sb + (wm * 64 + lr) * A_ROW_B + ko * 32 + lc * 16;
        uint32_t aB = sb + OFF_B + (ko * 16 + lr) * B_ROW_B + wn * 128 + lc * 16;
#pragma unroll
        for (int nj = 0; nj < 4; nj++) ldsm4t(bfr[pb][nj], aB + nj * 32);
#pragma unroll
        for (int mi = 0; mi < 4; mi++) ldsm4(afr[pb][mi], aA + mi * 16 * A_ROW_B);
    };

    load_stage(0); cp_commit();
    load_stage(1); cp_commit();

    for (int ck = 0; ck < NCH; ck++) {
        cp_wait1();
        __syncthreads();
        uint32_t sb = smem0 + (ck % NSTAGE) * STAGE_B;
        load_frags(0, 0, sb);                 // prime ko=0 frags ASAP
        if (ck + 2 < NCH) load_stage(ck + 2); // then hide gmem prefetch
        cp_commit();

#pragma unroll
        for (int ko = 0; ko < 4; ko++) {
            const int cur = ko & 1;
            if (ko < 3) load_frags(ko + 1, cur ^ 1, sb);  // prefetch next frags
#pragma unroll
            for (int mi = 0; mi < 4; mi++)
#pragma unroll
                for (int nj = 0; nj < 4; nj++) {
                    mma4(c[mi][2 * nj],     afr[cur][mi], bfr[cur][nj][0], bfr[cur][nj][1]);
                    mma4(c[mi][2 * nj + 1], afr[cur][mi], bfr[cur][nj][2], bfr[cur][nj][3]);
                }
        }
    }
    cp_wait0();
    __syncthreads();   // all compute done -> smem reusable for epilogue staging

    // ---- epilogue ----
    if constexpr (G1) {
        // swiglu on interleaved (a,b) pairs, stage through smem, vector stores
        __half* ep = reinterpret_cast<__half*>(dsm + wid * 64 * EP_STRIDE_B);
        const int q = lane & 3, lrow = lane >> 2;
#pragma unroll
        for (int mi = 0; mi < 4; mi++) {
            int r0 = mi * 16 + lrow;
#pragma unroll
            for (int n8 = 0; n8 < 8; n8++) {
                int col = n8 * 4 + q;
                float a0 = c[mi][n8][0], b0 = c[mi][n8][1];
                float a1 = c[mi][n8][2], b1 = c[mi][n8][3];
                float s0 = a0 / (1.0f + expf(-a0)) * b0;
                float s1 = a1 / (1.0f + expf(-a1)) * b1;
                *reinterpret_cast<__half*>(
                    reinterpret_cast<char*>(ep) + r0 * EP_STRIDE_B + col * 2) =
                    __float2half_rn(s0);
                *reinterpret_cast<__half*>(
                    reinterpret_cast<char*>(ep) + (r0 + 8) * EP_STRIDE_B + col * 2) =
                    __float2half_rn(s1);
            }
        }
        __syncwarp();
        const int fb = (nbase >> 1) + wn * 32;
#pragma unroll
        for (int j = 0; j < 8; j++) {
            int row = j * 8 + lrow;
            int gm = mbase + wm * 64 + row;
            if (gm < nrows) {
                uint4 v = *reinterpret_cast<const uint4*>(
                    reinterpret_cast<char*>(ep) + row * EP_STRIDE_B + q * 16);
                *reinterpret_cast<uint4*>(
                    &g_s[(size_t)(row0 + gm) * FDIM + fb + q * 8]) = v;
            }
        }
    } else {
        const int q = lane & 3, lrow = lane >> 2;
#pragma unroll
        for (int mi = 0; mi < 4; mi++) {
            int r0 = wm * 64 + mi * 16 + lrow;
            int gm0 = mbase + r0, gm1 = gm0 + 8;
            bool ok0 = gm0 < nrows, ok1 = gm1 < nrows;
            int tok0 = ok0 ? g_tok[row0 + gm0] : 0;
            int tok1 = ok1 ? g_tok[row0 + gm1] : 0;
            float w0 = ok0 ? g_w[row0 + gm0] : 0.0f;
            float w1v = ok1 ? g_w[row0 + gm1] : 0.0f;
            float* o0 = out + (size_t)tok0 * HDIM;
            float* o1 = out + (size_t)tok1 * HDIM;
#pragma unroll
            for (int n8 = 0; n8 < 8; n8++) {
                int col = nbase + wn * 64 + n8 * 8 + q * 2;
                if (ok0) {
                    atomicAdd(o0 + col,     w0 * c[mi][n8][0]);
                    atomicAdd(o0 + col + 1, w0 * c[mi][n8][1]);
                }
                if (ok1) {
                    atomicAdd(o1 + col,     w1v * c[mi][n8][2]);
                    atomicAdd(o1 + col + 1, w1v * c[mi][n8][3]);
                }
            }
        }
    }
}

// ---------------------------------------------------------------------------
// launch — ordered so gemm_tc<true> is the 6th launch (ncu -s 5 -c 1 target)
// ---------------------------------------------------------------------------
extern "C" void kernel_launch(void* const* d_in, const int* in_sizes, int n_in,
                              void* d_out, int out_size) {
    const float* x  = (const float*)d_in[0]; // [T, H]
    const float* gw = (const float*)d_in[1]; // [E, H]
    const float* w1 = (const float*)d_in[2]; // [E, H, 2F]
    const float* w2 = (const float*)d_in[3]; // [E, F, H]
    float* out = (float*)d_out;              // [T, H]

    cudaFuncSetAttribute(gemm_tc<true>,  cudaFuncAttributeMaxDynamicSharedMemorySize, SMEM_TOTAL);
    cudaFuncSetAttribute(gemm_tc<false>, cudaFuncAttributeMaxDynamicSharedMemorySize, SMEM_TOTAL);

    // #1: x conversion (+ counter zeroing)
    convert_x_kernel<<<(T_TOK * HDIM / 8) / 256, 256>>>(x);
    // #2-#4: routing
    gate_kernel<<<T_TOK / 8, 256>>>(x, gw);
    scan_kernel<<<1, 1>>>();
    scatter_kernel<<<T_TOK / 256, 256>>>();
    // #5: w1 conversion
    convert_w1i_kernel<<<(NEXP * HDIM * (FDIM / 4)) / 256, 256>>>(w1);
    // #6: GEMM1 (ncu capture target)
    gemm_tc<true ><<<dim3(2 * FDIM / BN, MTILES_MAX, NEXP), 256, SMEM_TOTAL>>>(out);
    // #7-#8: out reset + w2 conversion
    reset_kernel<<<8192, 1024>>>(out);
    convert_w2s_kernel<<<(int)(((size_t)NEXP * FDIM * HDIM / 8) / 256), 256>>>(w2);
    // #9: GEMM2
    gemm_tc<false><<<dim3(HDIM / BN, MTILES_MAX, NEXP), 256, SMEM_TOTAL>>>(out);
}